// round 11
// baseline (speedup 1.0000x reference)
#include <cuda_runtime.h>
#include <cstdint>

// CubicalLayer gather: out[i] = X[indices[i].row * 4096 + indices[i].col]
// X: 4096x4096 fp32 (64MB), indices: 524288 x 2 int32, out: 524288 fp32.
//
// R11: same proven max-MLP structure as the 8.67us best (int4 idx loads ->
// 4 independent gathers -> float4 store), but finer-grained blocks
// (128 threads x 1024 blocks instead of 256 x 512): halves the per-CTA
// front-batched LDG burst into the L1tex queue and doubles the number of
// schedulable work units, shrinking the slowest-CTA tail (B300 cross-CTA
// L1tex-queue spread model). Everything else over 10 rounds was invariant:
// this access pattern is at the memory system's divergent-transaction
// service wall.

#define W_SHIFT 12   // table row stride 4096

__global__ void __launch_bounds__(128) cubical_gather_kernel(
    const float* __restrict__ X,
    const int4* __restrict__ idx4,   // indices as int4: {r0,c0,r1,c1}
    float4* __restrict__ out4,
    int n_vec)                        // number of float4 outputs
{
    int t = blockIdx.x * blockDim.x + threadIdx.x;
    if (t >= n_vec) return;

    // Two int4 loads = 4 (row,col) pairs for outputs [4t .. 4t+3]
    int4 p = __ldg(&idx4[2 * t]);
    int4 q = __ldg(&idx4[2 * t + 1]);

    // All addresses first so ptxas front-batches the 4 independent gathers.
    int o0 = (p.x << W_SHIFT) + p.y;
    int o1 = (p.z << W_SHIFT) + p.w;
    int o2 = (q.x << W_SHIFT) + q.y;
    int o3 = (q.z << W_SHIFT) + q.w;

    float4 v;
    v.x = __ldg(X + o0);
    v.y = __ldg(X + o1);
    v.z = __ldg(X + o2);
    v.w = __ldg(X + o3);

    out4[t] = v;
}

extern "C" void kernel_launch(void* const* d_in, const int* in_sizes, int n_in,
                              void* d_out, int out_size)
{
    const float* X   = (const float*)d_in[0];   // 4096*4096 fp32
    const int*   idx = (const int*)d_in[1];     // N_IDX*2 int32

    int n_out = out_size;        // 524288 fp32 elements
    int n_vec = n_out / 4;       // 131072 float4 outputs

    int threads = 128;
    int blocks  = (n_vec + threads - 1) / threads;   // 1024

    cubical_gather_kernel<<<blocks, threads>>>(
        X, (const int4*)idx, (float4*)d_out, n_vec);
}

// round 12
// speedup vs baseline: 1.0037x; 1.0037x over previous
#include <cuda_runtime.h>
#include <cstdint>

// CubicalLayer gather: out[i] = X[indices[i].row * 4096 + indices[i].col]
// X: 4096x4096 fp32 (64MB), indices: 524288 x 2 int32, out: 524288 fp32.
//
// FINAL (best measured: 8.672us). 524288 fully-divergent 4B gathers saturate
// the GB300 memory system's transaction service rate (~60G/s; DRAM 52%-active
// at 4.2TB/s = random-access ceiling). Exhaustively verified invariants over
// 11 rounds:
//   - occupancy 37%..77%, MLP 2..4/thread, block 128/256: all within ±3%
//   - L2 eviction policies & prefetch-size hints (NC and non-NC): neutral/worse
//   - streaming store hints: neutral
//   - address binning for DRAM row locality (2 designs): 6-10x WORSE
//     (bookkeeping traffic >> locality savings)
// Structure: int4 index loads -> 4 independent front-batched gathers ->
// float4 store. Simplest form at the hardware wall.

#define W_SHIFT 12   // table row stride 4096

__global__ void __launch_bounds__(256) cubical_gather_kernel(
    const float* __restrict__ X,
    const int4* __restrict__ idx4,   // indices as int4: {r0,c0,r1,c1}
    float4* __restrict__ out4,
    int n_vec)                        // number of float4 outputs
{
    int t = blockIdx.x * blockDim.x + threadIdx.x;
    if (t >= n_vec) return;

    // Two int4 loads = 4 (row,col) pairs for outputs [4t .. 4t+3]
    int4 p = __ldg(&idx4[2 * t]);
    int4 q = __ldg(&idx4[2 * t + 1]);

    // All addresses first so ptxas front-batches the 4 independent gathers.
    int o0 = (p.x << W_SHIFT) + p.y;
    int o1 = (p.z << W_SHIFT) + p.w;
    int o2 = (q.x << W_SHIFT) + q.y;
    int o3 = (q.z << W_SHIFT) + q.w;

    float4 v;
    v.x = __ldg(X + o0);
    v.y = __ldg(X + o1);
    v.z = __ldg(X + o2);
    v.w = __ldg(X + o3);

    out4[t] = v;
}

extern "C" void kernel_launch(void* const* d_in, const int* in_sizes, int n_in,
                              void* d_out, int out_size)
{
    const float* X   = (const float*)d_in[0];   // 4096*4096 fp32
    const int*   idx = (const int*)d_in[1];     // N_IDX*2 int32

    int n_out = out_size;        // 524288 fp32 elements
    int n_vec = n_out / 4;       // 131072 float4 outputs

    int threads = 256;
    int blocks  = (n_vec + threads - 1) / threads;   // 512

    cubical_gather_kernel<<<blocks, threads>>>(
        X, (const int4*)idx, (float4*)d_out, n_vec);
}